// round 2
// baseline (speedup 1.0000x reference)
#include <cuda_runtime.h>
#include <cuda_bf16.h>

#define DIM 64
#define NODES_MAX 100000

// Scratch for neighbor-sum aggregation (allocation-free rule: __device__ global).
__device__ float g_agg[(size_t)NODES_MAX * DIM];

// ---------------------------------------------------------------------------
// Kernel 1: zero the aggregation buffer (vectorized).
// ---------------------------------------------------------------------------
__global__ void zero_agg_kernel(int n4) {
    int i = blockIdx.x * blockDim.x + threadIdx.x;
    if (i < n4) {
        ((float4*)g_agg)[i] = make_float4(0.f, 0.f, 0.f, 0.f);
    }
}

// ---------------------------------------------------------------------------
// Kernel 2: edge scatter-add. One thread per (edge, 4-feature chunk).
// 16 threads cooperate on one edge; float4 atomics (sm_90+) cut RED count 4x.
// x and agg both fit in L2 (25.6 MB each), so this is L2-bound.
// ---------------------------------------------------------------------------
__global__ void scatter_kernel(const float* __restrict__ x,
                               const int* __restrict__ src,
                               const int* __restrict__ dst,
                               int E) {
    long long g = (long long)blockIdx.x * blockDim.x + threadIdx.x;
    int e = (int)(g >> 4);
    int c = (int)(g & 15);
    if (e >= E) return;
    int s = __ldg(src + e);
    int d = __ldg(dst + e);
    float4 v = ((const float4*)x)[(long long)s * 16 + c];
    atomicAdd(((float4*)g_agg) + ((long long)d * 16 + c), v);
}

// ---------------------------------------------------------------------------
// Kernel 3: fused MLP per 64-node tile.
//   h   = x + agg
//   h1  = relu(h @ W1 + b1)
//   h2  = h1 @ W2 + b2
//   out = x + relu(h2)
//
// Shared: ONE weight buffer Ws (16 KB), time-multiplexed W1 -> W2 at the
// layer boundary, plus feature-major h tile hs[f][n] (stride 68 keeps float4
// accesses 16B-aligned). Total ~34 KB < 48 KB static limit.
// 256 threads = 16 col-groups x 16 node-groups; each thread owns a
// 4-node x 4-col register tile. Per k-step: one LDS.128 (h, 4 nodes) +
// one LDS.128 (W, 4 cols) feed 16 FMA.
// ---------------------------------------------------------------------------
__global__ __launch_bounds__(256) void mlp_kernel(const float* __restrict__ x,
                                                  const float* __restrict__ W1,
                                                  const float* __restrict__ b1,
                                                  const float* __restrict__ W2,
                                                  const float* __restrict__ b2,
                                                  float* __restrict__ out,
                                                  int N) {
    __shared__ float Ws[64 * 64];
    __shared__ float b1s[64];
    __shared__ float b2s[64];
    __shared__ float hs[64 * 68];   // hs[f * 68 + n], n in [0,64)

    const int tid = threadIdx.x;

    // Load W1 (1024 float4, 256 threads -> 4 each) + biases.
    for (int i = tid; i < 64 * 16; i += 256) {
        ((float4*)Ws)[i] = ((const float4*)W1)[i];
    }
    if (tid < 64) {
        b1s[tid] = b1[tid];
        b2s[tid] = b2[tid];
    }

    const int node0 = blockIdx.x * 64;

    // Load h = x + agg, transposed into feature-major hs[f][n].
    for (int i = tid; i < 64 * 16; i += 256) {
        int n  = i >> 4;   // local node 0..63
        int f4 = i & 15;   // feature float4 index 0..15
        int node = node0 + n;
        float4 v;
        if (node < N) {
            float4 xv = ((const float4*)x)[(long long)node * 16 + f4];
            float4 av = ((const float4*)g_agg)[(long long)node * 16 + f4];
            v = make_float4(xv.x + av.x, xv.y + av.y, xv.z + av.z, xv.w + av.w);
        } else {
            v = make_float4(0.f, 0.f, 0.f, 0.f);
        }
        int f = f4 * 4;
        hs[(f + 0) * 68 + n] = v.x;
        hs[(f + 1) * 68 + n] = v.y;
        hs[(f + 2) * 68 + n] = v.z;
        hs[(f + 3) * 68 + n] = v.w;
    }
    __syncthreads();

    const int tc = tid & 15;   // col group: cols tc*4 .. tc*4+3
    const int tn = tid >> 4;   // node group: nodes tn*4 .. tn*4+3

    // ---------------- Layer 1: h1 = relu(h @ W1 + b1) ----------------
    float acc[4][4];
    {
        float4 bv = *(const float4*)&b1s[tc * 4];
        #pragma unroll
        for (int i = 0; i < 4; i++) {
            acc[i][0] = bv.x; acc[i][1] = bv.y; acc[i][2] = bv.z; acc[i][3] = bv.w;
        }
        #pragma unroll 4
        for (int k = 0; k < 64; k++) {
            float4 w  = *(const float4*)&Ws[k * 64 + tc * 4];
            float4 hv = *(const float4*)&hs[k * 68 + tn * 4];
            acc[0][0] += hv.x * w.x; acc[0][1] += hv.x * w.y; acc[0][2] += hv.x * w.z; acc[0][3] += hv.x * w.w;
            acc[1][0] += hv.y * w.x; acc[1][1] += hv.y * w.y; acc[1][2] += hv.y * w.z; acc[1][3] += hv.y * w.w;
            acc[2][0] += hv.z * w.x; acc[2][1] += hv.z * w.y; acc[2][2] += hv.z * w.z; acc[2][3] += hv.z * w.w;
            acc[3][0] += hv.w * w.x; acc[3][1] += hv.w * w.y; acc[3][2] += hv.w * w.z; acc[3][3] += hv.w * w.w;
        }
    }
    __syncthreads();   // layer-1 reads of hs AND Ws complete

    // ReLU + transposed writeback hs[col][node]; concurrently swap W1 -> W2.
    #pragma unroll
    for (int j = 0; j < 4; j++) {
        int c = tc * 4 + j;
        float4 sv = make_float4(fmaxf(acc[0][j], 0.f), fmaxf(acc[1][j], 0.f),
                                fmaxf(acc[2][j], 0.f), fmaxf(acc[3][j], 0.f));
        *(float4*)&hs[c * 68 + tn * 4] = sv;
    }
    for (int i = tid; i < 64 * 16; i += 256) {
        ((float4*)Ws)[i] = ((const float4*)W2)[i];   // L2-resident, ~cheap
    }
    __syncthreads();

    // ---------------- Layer 2: h2 = h1 @ W2 + b2 ----------------
    {
        float4 bv = *(const float4*)&b2s[tc * 4];
        #pragma unroll
        for (int i = 0; i < 4; i++) {
            acc[i][0] = bv.x; acc[i][1] = bv.y; acc[i][2] = bv.z; acc[i][3] = bv.w;
        }
        #pragma unroll 4
        for (int k = 0; k < 64; k++) {
            float4 w  = *(const float4*)&Ws[k * 64 + tc * 4];
            float4 hv = *(const float4*)&hs[k * 68 + tn * 4];
            acc[0][0] += hv.x * w.x; acc[0][1] += hv.x * w.y; acc[0][2] += hv.x * w.z; acc[0][3] += hv.x * w.w;
            acc[1][0] += hv.y * w.x; acc[1][1] += hv.y * w.y; acc[1][2] += hv.y * w.z; acc[1][3] += hv.y * w.w;
            acc[2][0] += hv.z * w.x; acc[2][1] += hv.z * w.y; acc[2][2] += hv.z * w.z; acc[2][3] += hv.z * w.w;
            acc[3][0] += hv.w * w.x; acc[3][1] += hv.w * w.y; acc[3][2] += hv.w * w.z; acc[3][3] += hv.w * w.w;
        }
    }

    // Epilogue: out = x + relu(h2)
    #pragma unroll
    for (int i = 0; i < 4; i++) {
        int node = node0 + tn * 4 + i;
        if (node < N) {
            float4 xv = ((const float4*)x)[(long long)node * 16 + tc];
            float4 ov = make_float4(xv.x + fmaxf(acc[i][0], 0.f),
                                    xv.y + fmaxf(acc[i][1], 0.f),
                                    xv.z + fmaxf(acc[i][2], 0.f),
                                    xv.w + fmaxf(acc[i][3], 0.f));
            ((float4*)out)[(long long)node * 16 + tc] = ov;
        }
    }
}

// ---------------------------------------------------------------------------
// Launch
// ---------------------------------------------------------------------------
extern "C" void kernel_launch(void* const* d_in, const int* in_sizes, int n_in,
                              void* d_out, int out_size) {
    const float* x   = (const float*)d_in[0];
    const int*   ei  = (const int*)d_in[1];
    const float* W1  = (const float*)d_in[2];
    const float* b1  = (const float*)d_in[3];
    const float* W2  = (const float*)d_in[4];
    const float* b2  = (const float*)d_in[5];
    float* out = (float*)d_out;

    int N = in_sizes[0] / DIM;       // 100000
    int E = in_sizes[1] / 2;         // 1600000
    const int* src = ei;
    const int* dst = ei + E;

    // 1. zero aggregation buffer
    int n4 = N * (DIM / 4);
    zero_agg_kernel<<<(n4 + 255) / 256, 256>>>(n4);

    // 2. scatter-add neighbor features
    long long threads = (long long)E * 16;
    int sblocks = (int)((threads + 255) / 256);
    scatter_kernel<<<sblocks, 256>>>(x, src, dst, E);

    // 3. fused MLP + residual
    int mblocks = (N + 63) / 64;
    mlp_kernel<<<mblocks, 256>>>(x, W1, b1, W2, b2, out, N);
}